// round 1
// baseline (speedup 1.0000x reference)
#include <cuda_runtime.h>
#include <cstdint>
#include <cstddef>

// Problem dims (fixed by the dataset)
#define NB 4
#define SEQ 2048
#define NH 16
#define HD 64
#define DMODEL 1024

// Scratch for projected Q/K/V (allocation-free rule -> __device__ globals)
__device__ float g_q[NB * SEQ * DMODEL];
__device__ float g_k[NB * SEQ * DMODEL];
__device__ float g_v[NB * SEQ * DMODEL];

__device__ __forceinline__ uint32_t f2tf(float x) {
    uint32_t r;
    asm("cvt.rna.tf32.f32 %0, %1;" : "=r"(r) : "f"(x));
    return r;
}
__device__ __forceinline__ float f2tff(float x) { return __uint_as_float(f2tf(x)); }
__device__ __forceinline__ uint32_t fb(float x) { return __float_as_uint(x); }

__device__ __forceinline__ void mma_tf32(float c[4], const uint32_t a[4], uint32_t b0, uint32_t b1) {
    asm volatile(
        "mma.sync.aligned.m16n8k8.row.col.f32.tf32.tf32.f32 "
        "{%0,%1,%2,%3}, {%4,%5,%6,%7}, {%8,%9}, {%0,%1,%2,%3};\n"
        : "+f"(c[0]), "+f"(c[1]), "+f"(c[2]), "+f"(c[3])
        : "r"(a[0]), "r"(a[1]), "r"(a[2]), "r"(a[3]), "r"(b0), "r"(b1));
}

// ============================================================================
// Kernel 1: fused projections  out = X @ W + b  for Q, K, V (grid.z selects)
// Block tile 128x128, BK=16, 256 threads = 8 warps (4 m x 2 n), warp 32x64.
// ============================================================================
__global__ __launch_bounds__(256, 1) void proj_kernel(
    const float* __restrict__ xq, const float* __restrict__ xk, const float* __restrict__ xv,
    const float* __restrict__ Wq, const float* __restrict__ bq,
    const float* __restrict__ Wk, const float* __restrict__ bk,
    const float* __restrict__ Wv, const float* __restrict__ bv)
{
    __shared__ float As[128][20];   // [m][k], pad 20 -> conflict-free frag reads
    __shared__ float Bs[16][132];   // [k][n], pad 132 (16B-aligned rows)

    const float* X; const float* W; const float* bias; float* out;
    if (blockIdx.z == 0)      { X = xq; W = Wq; bias = bq; out = g_q; }
    else if (blockIdx.z == 1) { X = xk; W = Wk; bias = bk; out = g_k; }
    else                      { X = xv; W = Wv; bias = bv; out = g_v; }

    const int tid = threadIdx.x;
    const int warp = tid >> 5, lane = tid & 31;
    const int wm = warp >> 1, wn = warp & 1;
    const int gi = lane >> 2, tg = lane & 3;
    const int m0 = blockIdx.y * 128, n0 = blockIdx.x * 128;

    float acc[2][8][4];
    #pragma unroll
    for (int i = 0; i < 2; i++)
        #pragma unroll
        for (int j = 0; j < 8; j++)
            #pragma unroll
            for (int c = 0; c < 4; c++) acc[i][j][c] = 0.f;

    for (int kk = 0; kk < DMODEL; kk += 16) {
        // A tile: 128 rows x 16 cols = 512 float4
        #pragma unroll
        for (int i = 0; i < 2; i++) {
            int idx = tid + i * 256;
            int r = idx >> 2, c4 = idx & 3;
            float4 v = *(const float4*)(X + (size_t)(m0 + r) * DMODEL + kk + c4 * 4);
            float4 w; w.x = f2tff(v.x); w.y = f2tff(v.y); w.z = f2tff(v.z); w.w = f2tff(v.w);
            *(float4*)&As[r][c4 * 4] = w;
        }
        // B tile: 16 rows x 128 cols = 512 float4
        #pragma unroll
        for (int i = 0; i < 2; i++) {
            int idx = tid + i * 256;
            int r = idx >> 5, c4 = idx & 31;
            float4 v = *(const float4*)(W + (size_t)(kk + r) * DMODEL + n0 + c4 * 4);
            float4 w; w.x = f2tff(v.x); w.y = f2tff(v.y); w.z = f2tff(v.z); w.w = f2tff(v.w);
            *(float4*)&Bs[r][c4 * 4] = w;
        }
        __syncthreads();

        #pragma unroll
        for (int ks = 0; ks < 2; ks++) {
            const int kb = ks * 8;
            uint32_t a[2][4];
            #pragma unroll
            for (int mf = 0; mf < 2; mf++) {
                int m = wm * 32 + mf * 16;
                a[mf][0] = fb(As[m + gi][kb + tg]);
                a[mf][1] = fb(As[m + gi + 8][kb + tg]);
                a[mf][2] = fb(As[m + gi][kb + tg + 4]);
                a[mf][3] = fb(As[m + gi + 8][kb + tg + 4]);
            }
            #pragma unroll
            for (int nf = 0; nf < 8; nf++) {
                int n = wn * 64 + nf * 8 + gi;
                uint32_t b0 = fb(Bs[kb + tg][n]);
                uint32_t b1 = fb(Bs[kb + tg + 4][n]);
                mma_tf32(acc[0][nf], a[0], b0, b1);
                mma_tf32(acc[1][nf], a[1], b0, b1);
            }
        }
        __syncthreads();
    }

    #pragma unroll
    for (int mf = 0; mf < 2; mf++) {
        int m = m0 + wm * 32 + mf * 16 + gi;
        #pragma unroll
        for (int nf = 0; nf < 8; nf++) {
            int n = n0 + wn * 64 + nf * 8 + 2 * tg;
            float bb0 = bias[n], bb1 = bias[n + 1];
            *(float2*)(out + (size_t)m * DMODEL + n) =
                make_float2(acc[mf][nf][0] + bb0, acc[mf][nf][1] + bb1);
            *(float2*)(out + (size_t)(m + 8) * DMODEL + n) =
                make_float2(acc[mf][nf][2] + bb0, acc[mf][nf][3] + bb1);
        }
    }
}

// ============================================================================
// Kernel 2: attention with softmax over the BATCH axis.
// Block = (head h, q-tile of 64). 256 threads = 8 warps = (4 q-warps x 2).
// Tiles (all 4 batches): Qs[4][64][68], Ks[4][64][68] (reused for P), Vs same.
// Per k-tile: S_b = Q_b K_b^T (tf32 mma) -> elementwise softmax across b
// (mask term rounded separately, matching fp32 reference) -> P to smem ->
// O_b += P_b V_b (tf32 mma). O accumulated in registers across k-tiles.
// ============================================================================
#define TPAD 68
#define TILE_F (4 * 64 * TPAD)
#define ATTN_SMEM (3 * TILE_F * (int)sizeof(float))   // 208896 B

__device__ __forceinline__ void load_tile_tf32(float* dst, const float* __restrict__ src,
                                               int row0, int h, int tid)
{
    #pragma unroll
    for (int i = 0; i < 16; i++) {
        int idx = tid + i * 256;          // 0..4095 float4s
        int b = idx >> 10;
        int r = (idx >> 4) & 63;
        int c4 = idx & 15;
        float4 v = *(const float4*)(src + ((size_t)(b * SEQ + row0 + r) << 10) + (h << 6) + (c4 << 2));
        float4 w; w.x = f2tff(v.x); w.y = f2tff(v.y); w.z = f2tff(v.z); w.w = f2tff(v.w);
        *(float4*)(dst + (b * 64 + r) * TPAD + c4 * 4) = w;
    }
}

__global__ __launch_bounds__(256, 1) void attn_kernel(const float* __restrict__ mask,
                                                      float* __restrict__ out)
{
    extern __shared__ float sm[];
    float* Qs = sm;
    float* Ks = sm + TILE_F;        // also holds P after softmax
    float* Vs = sm + 2 * TILE_F;

    const int h = blockIdx.x, qt = blockIdx.y;
    const int tid = threadIdx.x;
    const int warp = tid >> 5, lane = tid & 31;
    const int wq = warp >> 1, wk = warp & 1;   // wk = k-half for S, d-half for O
    const int gi = lane >> 2, tg = lane & 3;
    const int qb = wq * 16, kb = wk * 32;
    const int q0 = qt * 64;

    load_tile_tf32(Qs, g_q, q0, h, tid);

    float O[4][4][4];
    #pragma unroll
    for (int b = 0; b < 4; b++)
        #pragma unroll
        for (int nf = 0; nf < 4; nf++)
            #pragma unroll
            for (int c = 0; c < 4; c++) O[b][nf][c] = 0.f;

    for (int k0 = 0; k0 < SEQ; k0 += 64) {
        __syncthreads();                    // prev iter's PV done before overwrite
        load_tile_tf32(Ks, g_k, k0, h, tid);
        load_tile_tf32(Vs, g_v, k0, h, tid);
        __syncthreads();

        // ---- S_b = Q_b K_b^T ----
        float S[4][4][4];
        #pragma unroll
        for (int b = 0; b < 4; b++)
            #pragma unroll
            for (int nf = 0; nf < 4; nf++)
                #pragma unroll
                for (int c = 0; c < 4; c++) S[b][nf][c] = 0.f;

        #pragma unroll
        for (int b = 0; b < 4; b++) {
            const float* Qb = Qs + b * 64 * TPAD;
            const float* Kb = Ks + b * 64 * TPAD;
            #pragma unroll
            for (int ds = 0; ds < 8; ds++) {
                int d = ds * 8 + tg;
                uint32_t a[4];
                a[0] = fb(Qb[(qb + gi) * TPAD + d]);
                a[1] = fb(Qb[(qb + gi + 8) * TPAD + d]);
                a[2] = fb(Qb[(qb + gi) * TPAD + d + 4]);
                a[3] = fb(Qb[(qb + gi + 8) * TPAD + d + 4]);
                #pragma unroll
                for (int nf = 0; nf < 4; nf++) {
                    int kr = kb + nf * 8 + gi;
                    uint32_t b0 = fb(Kb[kr * TPAD + d]);
                    uint32_t b1 = fb(Kb[kr * TPAD + d + 4]);
                    mma_tf32(S[b][nf], a, b0, b1);
                }
            }
        }
        __syncthreads();                    // done reading K before P overwrites it

        // ---- softmax over batch axis, write P into Ks ----
        #pragma unroll
        for (int nf = 0; nf < 4; nf++) {
            int klo = kb + nf * 8 + 2 * tg;
            #pragma unroll
            for (int half = 0; half < 2; half++) {
                int ql = qb + gi + half * 8;
                size_t moff = (size_t)(q0 + ql) * SEQ + k0 + klo;
                float2 mv[4];
                #pragma unroll
                for (int b = 0; b < 4; b++)
                    mv[b] = *(const float2*)(mask + (size_t)b * SEQ * SEQ + moff);
                #pragma unroll
                for (int j = 0; j < 2; j++) {
                    float z[4];
                    #pragma unroll
                    for (int b = 0; b < 4; b++) {
                        float mm = j ? mv[b].y : mv[b].x;
                        // round product BEFORE add (matches reference fp32 semantics)
                        z[b] = __fadd_rn(__fmul_rn(S[b][nf][half * 2 + j], 0.125f),
                                         __fmul_rn(mm, -1e9f));
                    }
                    float mx = fmaxf(fmaxf(z[0], z[1]), fmaxf(z[2], z[3]));
                    float e[4];
                    #pragma unroll
                    for (int b = 0; b < 4; b++) e[b] = __expf(z[b] - mx);
                    float s = (e[0] + e[1]) + (e[2] + e[3]);
                    float inv = __fdividef(1.0f, s);
                    #pragma unroll
                    for (int b = 0; b < 4; b++)
                        Ks[b * 64 * TPAD + ql * TPAD + klo + j] = f2tff(e[b] * inv);
                }
            }
        }
        __syncthreads();                    // P fully written

        // ---- O_b += P_b V_b  (warp's wk now indexes the d-half) ----
        #pragma unroll
        for (int b = 0; b < 4; b++) {
            const float* Pb = Ks + b * 64 * TPAD;
            const float* Vb = Vs + b * 64 * TPAD;
            #pragma unroll
            for (int ks = 0; ks < 8; ks++) {
                int kkk = ks * 8 + tg;
                uint32_t a[4];
                a[0] = fb(Pb[(qb + gi) * TPAD + kkk]);
                a[1] = fb(Pb[(qb + gi + 8) * TPAD + kkk]);
                a[2] = fb(Pb[(qb + gi) * TPAD + kkk + 4]);
                a[3] = fb(Pb[(qb + gi + 8) * TPAD + kkk + 4]);
                #pragma unroll
                for (int nf = 0; nf < 4; nf++) {
                    int dd = kb + nf * 8 + gi;
                    uint32_t b0 = fb(Vb[(ks * 8 + tg) * TPAD + dd]);
                    uint32_t b1 = fb(Vb[(ks * 8 + tg + 4) * TPAD + dd]);
                    mma_tf32(O[b][nf], a, b0, b1);
                }
            }
        }
    }

    // ---- epilogue: [B,H,S,D] -> [B,S,H*D] ----
    #pragma unroll
    for (int b = 0; b < 4; b++) {
        #pragma unroll
        for (int nf = 0; nf < 4; nf++) {
            int dglob = (h << 6) + kb + nf * 8 + 2 * tg;
            int qg = q0 + qb + gi;
            *(float2*)(out + ((size_t)b * SEQ + qg) * DMODEL + dglob) =
                make_float2(O[b][nf][0], O[b][nf][1]);
            *(float2*)(out + ((size_t)b * SEQ + qg + 8) * DMODEL + dglob) =
                make_float2(O[b][nf][2], O[b][nf][3]);
        }
    }
}

// ============================================================================
extern "C" void kernel_launch(void* const* d_in, const int* in_sizes, int n_in,
                              void* d_out, int out_size)
{
    (void)in_sizes; (void)n_in; (void)out_size;
    const float* xq   = (const float*)d_in[0];
    const float* xk   = (const float*)d_in[1];
    const float* xv   = (const float*)d_in[2];
    const float* mask = (const float*)d_in[3];
    const float* Wq   = (const float*)d_in[4];
    const float* bq   = (const float*)d_in[5];
    const float* Wk   = (const float*)d_in[6];
    const float* bk   = (const float*)d_in[7];
    const float* Wv   = (const float*)d_in[8];
    const float* bv   = (const float*)d_in[9];
    float* out = (float*)d_out;

    cudaFuncSetAttribute(attn_kernel, cudaFuncAttributeMaxDynamicSharedMemorySize, ATTN_SMEM);

    // Projections: grid (n-tiles, m-tiles, {q,k,v})
    proj_kernel<<<dim3(DMODEL / 128, (NB * SEQ) / 128, 3), 256>>>(
        xq, xk, xv, Wq, bq, Wk, bk, Wv, bv);

    // Attention: grid.x = head (fastest -> same-q blocks co-resident, mask reuse in L2)
    attn_kernel<<<dim3(NH, SEQ / 64), 256, ATTN_SMEM>>>(mask, out);
}

// round 2
// speedup vs baseline: 1.2611x; 1.2611x over previous
#include <cuda_runtime.h>
#include <cstdint>
#include <cstddef>

#define NB 4
#define SEQ 2048
#define NH 16
#define HD 64
#define DMODEL 1024

// Scratch (allocation-free rule -> __device__ globals)
__device__ float g_x[3u * 8192u * 1024u];    // tf32-rounded inputs
__device__ float g_wt[3u * 1024u * 1024u];   // W transposed [n][k], tf32-rounded
__device__ float g_q[NB * SEQ * DMODEL];     // tf32-rounded projections
__device__ float g_k[NB * SEQ * DMODEL];
__device__ float g_v[NB * SEQ * DMODEL];
__device__ float g_vt[NB * NH * HD * SEQ];   // V transposed per (b,h): [d][s]

// ---------------------------------------------------------------------------
__device__ __forceinline__ uint32_t f2tf(float x) {
    uint32_t r;
    asm("cvt.rna.tf32.f32 %0, %1;" : "=r"(r) : "f"(x));
    return r;
}
__device__ __forceinline__ float f2tff(float x) { return __uint_as_float(f2tf(x)); }

__device__ __forceinline__ void mma_tf32(float c[4], const uint32_t a[4], uint32_t b0, uint32_t b1) {
    asm volatile(
        "mma.sync.aligned.m16n8k8.row.col.f32.tf32.tf32.f32 "
        "{%0,%1,%2,%3}, {%4,%5,%6,%7}, {%8,%9}, {%0,%1,%2,%3};\n"
        : "+f"(c[0]), "+f"(c[1]), "+f"(c[2]), "+f"(c[3])
        : "r"(a[0]), "r"(a[1]), "r"(a[2]), "r"(a[3]), "r"(b0), "r"(b1));
}

__device__ __forceinline__ uint32_t s2u(const void* p) {
    return (uint32_t)__cvta_generic_to_shared(p);
}
__device__ __forceinline__ void ldsm4(uint32_t& r0, uint32_t& r1, uint32_t& r2, uint32_t& r3,
                                      uint32_t addr) {
    asm volatile("ldmatrix.sync.aligned.m8n8.x4.shared.b16 {%0,%1,%2,%3}, [%4];"
                 : "=r"(r0), "=r"(r1), "=r"(r2), "=r"(r3) : "r"(addr));
}
__device__ __forceinline__ void cpa16(uint32_t dst, const float* src) {
    asm volatile("cp.async.cg.shared.global [%0], [%1], 16;" :: "r"(dst), "l"(src));
}
__device__ __forceinline__ void cpa_commit() { asm volatile("cp.async.commit_group;"); }
template <int N> __device__ __forceinline__ void cpa_wait() {
    asm volatile("cp.async.wait_group %0;" :: "n"(N));
}

// ============================================================================
// prep 1: round X inputs to tf32 (enables cp.async copy loads in proj)
// ============================================================================
__global__ void round_x_kernel(const float4* __restrict__ xq,
                               const float4* __restrict__ xk,
                               const float4* __restrict__ xv) {
    const int z = blockIdx.y;
    const float4* src = (z == 0) ? xq : (z == 1) ? xk : xv;
    float4* dst = (float4*)g_x + (size_t)z * (8192u * 1024u / 4u);
    size_t i = (size_t)blockIdx.x * blockDim.x + threadIdx.x;
    float4 v = src[i];
    v.x = f2tff(v.x); v.y = f2tff(v.y); v.z = f2tff(v.z); v.w = f2tff(v.w);
    dst[i] = v;
}

// ============================================================================
// prep 2: transpose + round W  ->  g_wt[z][n][k]
// ============================================================================
__global__ void wtrans_kernel(const float* __restrict__ Wq,
                              const float* __restrict__ Wk,
                              const float* __restrict__ Wv) {
    __shared__ float smw[64][68];
    const int z = blockIdx.z;
    const float* W = (z == 0) ? Wq : (z == 1) ? Wk : Wv;
    float* Wt = g_wt + (size_t)z * 1024u * 1024u;
    const int k0 = blockIdx.y * 64, n0 = blockIdx.x * 64;
    const int tid = threadIdx.x;
    #pragma unroll
    for (int i = 0; i < 4; i++) {
        int idx = tid + i * 256, r = idx >> 4, c4 = idx & 15;
        float4 v = *(const float4*)(W + (size_t)(k0 + r) * 1024 + n0 + c4 * 4);
        v.x = f2tff(v.x); v.y = f2tff(v.y); v.z = f2tff(v.z); v.w = f2tff(v.w);
        *(float4*)&smw[r][c4 * 4] = v;
    }
    __syncthreads();
    #pragma unroll
    for (int i = 0; i < 4; i++) {
        int idx = tid + i * 256, n = idx >> 4, c4 = idx & 15;
        float4 w = make_float4(smw[c4 * 4 + 0][n], smw[c4 * 4 + 1][n],
                               smw[c4 * 4 + 2][n], smw[c4 * 4 + 3][n]);
        *(float4*)(Wt + (size_t)(n0 + n) * 1024 + k0 + c4 * 4) = w;
    }
}

// ============================================================================
// prep 3 (after proj): transpose V per (b,h)  ->  g_vt[(b,h,d)][s]
// ============================================================================
__global__ void vtrans_kernel() {
    __shared__ float smv[64][68];
    const int b = blockIdx.z, h = blockIdx.y, s0 = blockIdx.x * 64;
    const int tid = threadIdx.x;
    #pragma unroll
    for (int i = 0; i < 4; i++) {
        int idx = tid + i * 256, r = idx >> 4, c4 = idx & 15;
        float4 v = *(const float4*)(g_v + ((size_t)(b * SEQ + s0 + r) << 10) + h * 64 + c4 * 4);
        *(float4*)&smv[r][c4 * 4] = v;
    }
    __syncthreads();
    #pragma unroll
    for (int i = 0; i < 4; i++) {
        int idx = tid + i * 256, d = idx >> 4, c4 = idx & 15;
        float4 w = make_float4(smv[c4 * 4 + 0][d], smv[c4 * 4 + 1][d],
                               smv[c4 * 4 + 2][d], smv[c4 * 4 + 3][d]);
        *(float4*)(g_vt + ((size_t)((b * NH + h) * HD + d)) * SEQ + s0 + c4 * 4) = w;
    }
}

// ============================================================================
// Kernel: projections (X @ W + b), cp.async double-buffered, ldmatrix frags.
// Block 128x128, BK=16, 256 threads = 8 warps (4m x 2n). A:[m][k] B:[n][k].
// ============================================================================
#define PSTR 20
__global__ __launch_bounds__(256, 2) void proj_kernel(
    const float* __restrict__ bq, const float* __restrict__ bk, const float* __restrict__ bv) {
    __shared__ float As[2][128 * PSTR];
    __shared__ float Bs[2][128 * PSTR];

    const int z = blockIdx.z;
    const float* X  = g_x  + (size_t)z * 8192u * 1024u;
    const float* Wt = g_wt + (size_t)z * 1024u * 1024u;
    const float* bias = (z == 0) ? bq : (z == 1) ? bk : bv;
    float* out = (z == 0) ? g_q : (z == 1) ? g_k : g_v;

    const int m0 = blockIdx.y * 128, n0 = blockIdx.x * 128;
    const int tid = threadIdx.x, warp = tid >> 5, lane = tid & 31;
    const int wm = warp >> 1, wn = warp & 1;
    const int gi = lane >> 2, tg = lane & 3;
    const int mi = lane >> 3, r8 = lane & 7;
    const int aoff = ((mi & 1) * 8 + r8) * PSTR + (mi >> 1) * 4;   // A-pattern
    const int koff = ((mi >> 1) * 8 + r8) * PSTR + (mi & 1) * 4;   // B-pattern
    const uint32_t Aa[2] = { s2u(As[0]), s2u(As[1]) };
    const uint32_t Ba[2] = { s2u(Bs[0]), s2u(Bs[1]) };

    auto issue = [&](int s, int kk) {
        #pragma unroll
        for (int i = 0; i < 2; i++) {
            int idx = tid + i * 256, r = idx >> 2, c4 = idx & 3;
            cpa16(Aa[s] + (r * PSTR + c4 * 4) * 4, X + (size_t)(m0 + r) * 1024 + kk + c4 * 4);
        }
        #pragma unroll
        for (int i = 0; i < 2; i++) {
            int idx = tid + i * 256, n = idx >> 2, c4 = idx & 3;
            cpa16(Ba[s] + (n * PSTR + c4 * 4) * 4, Wt + (size_t)(n0 + n) * 1024 + kk + c4 * 4);
        }
        cpa_commit();
    };

    float acc[2][8][4];
    #pragma unroll
    for (int i = 0; i < 2; i++)
        #pragma unroll
        for (int j = 0; j < 8; j++)
            #pragma unroll
            for (int c = 0; c < 4; c++) acc[i][j][c] = 0.f;

    issue(0, 0);
    for (int t = 0; t < 64; t++) {
        if (t < 63) { issue((t + 1) & 1, (t + 1) * 16); cpa_wait<1>(); }
        else        { cpa_wait<0>(); }
        __syncthreads();

        const uint32_t abase = Aa[t & 1] + ((wm * 32) * PSTR + aoff) * 4;
        const uint32_t bbase = Ba[t & 1] + ((wn * 64) * PSTR + koff) * 4;
        #pragma unroll
        for (int ks = 0; ks < 2; ks++) {
            uint32_t a[2][4], bb[4][4];
            #pragma unroll
            for (int mf = 0; mf < 2; mf++)
                ldsm4(a[mf][0], a[mf][1], a[mf][2], a[mf][3],
                      abase + ks * 32 + mf * 16 * PSTR * 4);
            #pragma unroll
            for (int p = 0; p < 4; p++)
                ldsm4(bb[p][0], bb[p][1], bb[p][2], bb[p][3],
                      bbase + ks * 32 + p * 16 * PSTR * 4);
            #pragma unroll
            for (int mf = 0; mf < 2; mf++)
                #pragma unroll
                for (int p = 0; p < 4; p++) {
                    mma_tf32(acc[mf][2 * p],     a[mf], bb[p][0], bb[p][1]);
                    mma_tf32(acc[mf][2 * p + 1], a[mf], bb[p][2], bb[p][3]);
                }
        }
        __syncthreads();
    }

    #pragma unroll
    for (int mf = 0; mf < 2; mf++) {
        int m = m0 + wm * 32 + mf * 16 + gi;
        #pragma unroll
        for (int nf = 0; nf < 8; nf++) {
            int n = n0 + wn * 64 + nf * 8 + 2 * tg;
            float b0v = bias[n], b1v = bias[n + 1];
            *(float2*)(out + (size_t)m * DMODEL + n) =
                make_float2(f2tff(acc[mf][nf][0] + b0v), f2tff(acc[mf][nf][1] + b1v));
            *(float2*)(out + (size_t)(m + 8) * DMODEL + n) =
                make_float2(f2tff(acc[mf][nf][2] + b0v), f2tff(acc[mf][nf][3] + b1v));
        }
    }
}

// ============================================================================
// Kernel: attention, softmax over BATCH axis.
// 512 threads = 16 warps = wq(4, q 16-row) x wk(4, 16 k-cols / 16 d-cols).
// All fragment loads via ldmatrix.x4; tiles loaded with cp.async.
// ============================================================================
#define TPAD 68
#define TILE_F (4 * 64 * TPAD)
#define ATTN_SMEM (3 * TILE_F * (int)sizeof(float))   // 208896 B

__global__ __launch_bounds__(512, 1) void attn_kernel(const float* __restrict__ mask,
                                                      float* __restrict__ out) {
    extern __shared__ float sm[];
    float* Qs = sm;
    float* Ks = sm + TILE_F;          // holds P after softmax
    float* Vs = sm + 2 * TILE_F;      // transposed V: [b][d][k]
    const uint32_t Qa = s2u(Qs), Ka = s2u(Ks), Va = s2u(Vs);

    const int h = blockIdx.x, qt = blockIdx.y, q0 = qt * 64;
    const int tid = threadIdx.x, warp = tid >> 5, lane = tid & 31;
    const int wq = warp >> 2, wk = warp & 3;
    const int gi = lane >> 2, tg = lane & 3;
    const int qb = wq * 16, kb = wk * 16;
    const int mi = lane >> 3, r8 = lane & 7;
    const int aoff = ((mi & 1) * 8 + r8) * TPAD + (mi >> 1) * 4;   // A-pattern
    const int koff = ((mi >> 1) * 8 + r8) * TPAD + (mi & 1) * 4;   // B-pattern

    // Q tile (whole loop lifetime)
    #pragma unroll
    for (int i = 0; i < 8; i++) {
        int idx = tid + i * 512;
        int b = idx >> 10, r = (idx >> 4) & 63, c4 = idx & 15;
        cpa16(Qa + ((b * 64 + r) * TPAD + c4 * 4) * 4,
              g_q + ((size_t)(b * SEQ + q0 + r) << 10) + (h << 6) + (c4 << 2));
    }
    cpa_commit();

    float O[4][2][4];
    #pragma unroll
    for (int b = 0; b < 4; b++)
        #pragma unroll
        for (int nf = 0; nf < 2; nf++)
            #pragma unroll
            for (int c = 0; c < 4; c++) O[b][nf][c] = 0.f;

    for (int k0 = 0; k0 < SEQ; k0 += 64) {
        __syncthreads();   // prev PV reads of Ks/Vs done
        #pragma unroll
        for (int i = 0; i < 8; i++) {
            int idx = tid + i * 512;
            int b = idx >> 10, r = (idx >> 4) & 63, c4 = idx & 15;
            cpa16(Ka + ((b * 64 + r) * TPAD + c4 * 4) * 4,
                  g_k + ((size_t)(b * SEQ + k0 + r) << 10) + (h << 6) + (c4 << 2));
        }
        #pragma unroll
        for (int i = 0; i < 8; i++) {
            int idx = tid + i * 512;
            int b = idx >> 10, d = (idx >> 4) & 63, c4 = idx & 15;
            cpa16(Va + ((b * 64 + d) * TPAD + c4 * 4) * 4,
                  g_vt + ((size_t)((b * NH + h) * HD + d)) * SEQ + k0 + (c4 << 2));
        }
        cpa_commit();
        cpa_wait<0>();
        __syncthreads();

        // ---- S = Q K^T (per batch) ----
        float S[4][2][4];
        #pragma unroll
        for (int b = 0; b < 4; b++)
            #pragma unroll
            for (int nf = 0; nf < 2; nf++)
                #pragma unroll
                for (int c = 0; c < 4; c++) S[b][nf][c] = 0.f;

        #pragma unroll
        for (int b = 0; b < 4; b++) {
            const uint32_t qbase = Qa + ((b * 64 + qb) * TPAD + aoff) * 4;
            const uint32_t kbase = Ka + ((b * 64 + kb) * TPAD + koff) * 4;
            #pragma unroll
            for (int ds = 0; ds < 8; ds++) {
                uint32_t a[4], b0, b1, b2, b3;
                ldsm4(a[0], a[1], a[2], a[3], qbase + ds * 32);
                ldsm4(b0, b1, b2, b3, kbase + ds * 32);
                mma_tf32(S[b][0], a, b0, b1);
                mma_tf32(S[b][1], a, b2, b3);
            }
        }
        __syncthreads();   // K reads done; Ks becomes P

        // ---- softmax across batch, write P (tf32-rounded) into Ks ----
        #pragma unroll
        for (int nf = 0; nf < 2; nf++) {
            #pragma unroll
            for (int half = 0; half < 2; half++) {
                const int ql = qb + gi + half * 8;
                const int klo = kb + nf * 8 + 2 * tg;
                const float* mptr = mask + (size_t)(q0 + ql) * SEQ + k0 + klo;
                float2 mv[4];
                #pragma unroll
                for (int b = 0; b < 4; b++)
                    mv[b] = *(const float2*)(mptr + (size_t)b * SEQ * SEQ);
                float res[4][2];
                #pragma unroll
                for (int j = 0; j < 2; j++) {
                    float z[4];
                    #pragma unroll
                    for (int b = 0; b < 4; b++) {
                        float mm = j ? mv[b].y : mv[b].x;
                        z[b] = __fadd_rn(__fmul_rn(S[b][nf][half * 2 + j], 0.125f),
                                         __fmul_rn(mm, -1e9f));
                    }
                    float mx = fmaxf(fmaxf(z[0], z[1]), fmaxf(z[2], z[3]));
                    float e0 = __expf(z[0] - mx), e1 = __expf(z[1] - mx);
                    float e2 = __expf(z[2] - mx), e3 = __expf(z[3] - mx);
                    float inv = __fdividef(1.0f, (e0 + e1) + (e2 + e3));
                    res[0][j] = f2tff(e0 * inv);
                    res[1][j] = f2tff(e1 * inv);
                    res[2][j] = f2tff(e2 * inv);
                    res[3][j] = f2tff(e3 * inv);
                }
                #pragma unroll
                for (int b = 0; b < 4; b++)
                    *(float2*)&Ks[(b * 64 + ql) * TPAD + klo] =
                        make_float2(res[b][0], res[b][1]);
            }
        }
        __syncthreads();   // P visible

        // ---- O += P V ----
        #pragma unroll
        for (int b = 0; b < 4; b++) {
            const uint32_t pbase = Ka + ((b * 64 + qb) * TPAD + aoff) * 4;
            const uint32_t vbase = Va + ((b * 64 + kb) * TPAD + koff) * 4;
            #pragma unroll
            for (int ks = 0; ks < 8; ks++) {
                uint32_t a[4], b0, b1, b2, b3;
                ldsm4(a[0], a[1], a[2], a[3], pbase + ks * 32);
                ldsm4(b0, b1, b2, b3, vbase + ks * 32);
                mma_tf32(O[b][0], a, b0, b1);
                mma_tf32(O[b][1], a, b2, b3);
            }
        }
    }

    // ---- epilogue: [B,H,S,D] -> [B,S,H*D] ----
    #pragma unroll
    for (int b = 0; b < 4; b++) {
        #pragma unroll
        for (int nf = 0; nf < 2; nf++) {
            int dg = (h << 6) + kb + nf * 8 + 2 * tg;
            int qg = q0 + qb + gi;
            *(float2*)(out + ((size_t)b * SEQ + qg) * DMODEL + dg) =
                make_float2(O[b][nf][0], O[b][nf][1]);
            *(float2*)(out + ((size_t)b * SEQ + qg + 8) * DMODEL + dg) =
                make_float2(O[b][nf][2], O[b][nf][3]);
        }
    }
}

// ============================================================================
extern "C" void kernel_launch(void* const* d_in, const int* in_sizes, int n_in,
                              void* d_out, int out_size) {
    (void)in_sizes; (void)n_in; (void)out_size;
    const float* xq   = (const float*)d_in[0];
    const float* xk   = (const float*)d_in[1];
    const float* xv   = (const float*)d_in[2];
    const float* mask = (const float*)d_in[3];
    const float* Wq   = (const float*)d_in[4];
    const float* bq   = (const float*)d_in[5];
    const float* Wk   = (const float*)d_in[6];
    const float* bk   = (const float*)d_in[7];
    const float* Wv   = (const float*)d_in[8];
    const float* bv   = (const float*)d_in[9];
    float* out = (float*)d_out;

    cudaFuncSetAttribute(attn_kernel, cudaFuncAttributeMaxDynamicSharedMemorySize, ATTN_SMEM);

    round_x_kernel<<<dim3(8192, 3), 256>>>((const float4*)xq, (const float4*)xk, (const float4*)xv);
    wtrans_kernel<<<dim3(16, 16, 3), 256>>>(Wq, Wk, Wv);
    proj_kernel<<<dim3(DMODEL / 128, (NB * SEQ) / 128, 3), 256>>>(bq, bk, bv);
    vtrans_kernel<<<dim3(SEQ / 64, NH, NB), 256>>>();
    attn_kernel<<<dim3(NH, SEQ / 64), 512, ATTN_SMEM>>>(mask, out);
}

// round 4
// speedup vs baseline: 2.4892x; 1.9739x over previous
#include <cuda_runtime.h>
#include <cuda_fp16.h>
#include <cstdint>
#include <cstddef>

#define NB 4
#define SEQ 2048
#define NH 16
#define HD 64
#define DMODEL 1024

// Scratch (allocation-free rule -> __device__ globals), all fp16
__device__ __half g_x[3u * 8192u * 1024u];   // rounded inputs
__device__ __half g_wt[3u * 1024u * 1024u];  // W transposed [n][k]
__device__ __half g_q[NB * SEQ * DMODEL];    // Q pre-scaled by 0.125
__device__ __half g_k[NB * SEQ * DMODEL];
__device__ __half g_v[NB * SEQ * DMODEL];

// ---------------------------------------------------------------------------
__device__ __forceinline__ uint32_t s2u(const void* p) {
    return (uint32_t)__cvta_generic_to_shared(p);
}
__device__ __forceinline__ void ldsm4(uint32_t& r0, uint32_t& r1, uint32_t& r2, uint32_t& r3,
                                      uint32_t addr) {
    asm volatile("ldmatrix.sync.aligned.m8n8.x4.shared.b16 {%0,%1,%2,%3}, [%4];"
                 : "=r"(r0), "=r"(r1), "=r"(r2), "=r"(r3) : "r"(addr));
}
__device__ __forceinline__ void ldsm4t(uint32_t& r0, uint32_t& r1, uint32_t& r2, uint32_t& r3,
                                       uint32_t addr) {
    asm volatile("ldmatrix.sync.aligned.m8n8.x4.trans.shared.b16 {%0,%1,%2,%3}, [%4];"
                 : "=r"(r0), "=r"(r1), "=r"(r2), "=r"(r3) : "r"(addr));
}
__device__ __forceinline__ void cpa16(uint32_t dst, const void* src) {
    asm volatile("cp.async.cg.shared.global [%0], [%1], 16;" :: "r"(dst), "l"(src));
}
__device__ __forceinline__ void cpa_commit() { asm volatile("cp.async.commit_group;"); }
template <int N> __device__ __forceinline__ void cpa_wait() {
    asm volatile("cp.async.wait_group %0;" :: "n"(N));
}
// fp16 inputs, fp32 accumulate: same significand width as tf32, 2x rate, K=16
__device__ __forceinline__ void mma_f16(float c[4], const uint32_t a[4], uint32_t b0, uint32_t b1) {
    asm volatile(
        "mma.sync.aligned.m16n8k16.row.col.f32.f16.f16.f32 "
        "{%0,%1,%2,%3}, {%4,%5,%6,%7}, {%8,%9}, {%0,%1,%2,%3};\n"
        : "+f"(c[0]), "+f"(c[1]), "+f"(c[2]), "+f"(c[3])
        : "r"(a[0]), "r"(a[1]), "r"(a[2]), "r"(a[3]), "r"(b0), "r"(b1));
}

// ============================================================================
// prep 1: round X inputs to fp16
// ============================================================================
__global__ void round_x_kernel(const float4* __restrict__ xq,
                               const float4* __restrict__ xk,
                               const float4* __restrict__ xv) {
    const int z = blockIdx.y;
    const float4* src = (z == 0) ? xq : (z == 1) ? xk : xv;
    __half2* dst = (__half2*)(g_x + (size_t)z * 8388608u);
    size_t i = (size_t)blockIdx.x * blockDim.x + threadIdx.x;
    float4 v = src[i];
    dst[2 * i]     = __floats2half2_rn(v.x, v.y);
    dst[2 * i + 1] = __floats2half2_rn(v.z, v.w);
}

// ============================================================================
// prep 2: transpose + round W -> g_wt[z][n][k] fp16
// ============================================================================
__global__ void wtrans_kernel(const float* __restrict__ Wq,
                              const float* __restrict__ Wk,
                              const float* __restrict__ Wv) {
    __shared__ float smw[64][68];
    const int z = blockIdx.z;
    const float* W = (z == 0) ? Wq : (z == 1) ? Wk : Wv;
    __half* Wt = g_wt + (size_t)z * 1048576u;
    const int k0 = blockIdx.y * 64, n0 = blockIdx.x * 64;
    const int tid = threadIdx.x;
    #pragma unroll
    for (int i = 0; i < 4; i++) {
        int idx = tid + i * 256, r = idx >> 4, c4 = idx & 15;
        float4 v = *(const float4*)(W + (size_t)(k0 + r) * 1024 + n0 + c4 * 4);
        *(float4*)&smw[r][c4 * 4] = v;
    }
    __syncthreads();
    #pragma unroll
    for (int i = 0; i < 4; i++) {
        int idx = tid + i * 256, n = idx >> 4, c4 = idx & 15;
        __half* o = Wt + (size_t)(n0 + n) * 1024 + k0 + c4 * 4;
        *(__half2*)(o)     = __floats2half2_rn(smw[c4 * 4 + 0][n], smw[c4 * 4 + 1][n]);
        *(__half2*)(o + 2) = __floats2half2_rn(smw[c4 * 4 + 2][n], smw[c4 * 4 + 3][n]);
    }
}

// ============================================================================
// projections: X(fp16) @ W(fp16) + b, fp32 accum, out fp16.
// Block 128x128, BK=32, cp.async double-buffered, 256 threads (4m x 2n warps).
// ============================================================================
#define PSTR 40
__global__ __launch_bounds__(256, 2) void proj_kernel(
    const float* __restrict__ bq, const float* __restrict__ bk, const float* __restrict__ bv) {
    __shared__ __half As[2][128 * PSTR];
    __shared__ __half Bs[2][128 * PSTR];

    const int z = blockIdx.z;
    const __half* X  = g_x  + (size_t)z * 8388608u;
    const __half* Wt = g_wt + (size_t)z * 1048576u;
    const float* bias = (z == 0) ? bq : (z == 1) ? bk : bv;
    __half* out = (z == 0) ? g_q : (z == 1) ? g_k : g_v;
    const float scl = (z == 0) ? 0.125f : 1.0f;

    const int m0 = blockIdx.y * 128, n0 = blockIdx.x * 128;
    const int tid = threadIdx.x, warp = tid >> 5, lane = tid & 31;
    const int wm = warp >> 1, wn = warp & 1;
    const int gi = lane >> 2, tg = lane & 3;
    const int mi = lane >> 3, r8 = lane & 7;
    const uint32_t aoff2 = (((mi & 1) * 8 + r8) * PSTR + (mi >> 1) * 8) * 2;
    const uint32_t koff2 = (((mi >> 1) * 8 + r8) * PSTR + (mi & 1) * 8) * 2;
    const uint32_t Aa[2] = { s2u(As[0]), s2u(As[1]) };
    const uint32_t Ba[2] = { s2u(Bs[0]), s2u(Bs[1]) };

    auto issue = [&](int s, int kk) {
        #pragma unroll
        for (int i = 0; i < 2; i++) {
            int idx = tid + i * 256, r = idx >> 2, c8 = idx & 3;
            cpa16(Aa[s] + r * (PSTR * 2) + c8 * 16, X + (size_t)(m0 + r) * 1024 + kk + c8 * 8);
        }
        #pragma unroll
        for (int i = 0; i < 2; i++) {
            int idx = tid + i * 256, n = idx >> 2, c8 = idx & 3;
            cpa16(Ba[s] + n * (PSTR * 2) + c8 * 16, Wt + (size_t)(n0 + n) * 1024 + kk + c8 * 8);
        }
        cpa_commit();
    };

    float acc[2][8][4];
    #pragma unroll
    for (int i = 0; i < 2; i++)
        #pragma unroll
        for (int j = 0; j < 8; j++)
            #pragma unroll
            for (int c = 0; c < 4; c++) acc[i][j][c] = 0.f;

    issue(0, 0);
    for (int t = 0; t < 32; t++) {
        if (t < 31) { issue((t + 1) & 1, (t + 1) * 32); cpa_wait<1>(); }
        else        { cpa_wait<0>(); }
        __syncthreads();

        const uint32_t abase = Aa[t & 1] + (wm * 32) * (PSTR * 2) + aoff2;
        const uint32_t bbase = Ba[t & 1] + (wn * 64) * (PSTR * 2) + koff2;
        #pragma unroll
        for (int ks = 0; ks < 2; ks++) {
            uint32_t a[2][4], bb[4][4];
            #pragma unroll
            for (int mf = 0; mf < 2; mf++)
                ldsm4(a[mf][0], a[mf][1], a[mf][2], a[mf][3],
                      abase + ks * 32 + mf * 16 * PSTR * 2);
            #pragma unroll
            for (int p = 0; p < 4; p++)
                ldsm4(bb[p][0], bb[p][1], bb[p][2], bb[p][3],
                      bbase + ks * 32 + p * 16 * PSTR * 2);
            #pragma unroll
            for (int mf = 0; mf < 2; mf++)
                #pragma unroll
                for (int p = 0; p < 4; p++) {
                    mma_f16(acc[mf][2 * p],     a[mf], bb[p][0], bb[p][1]);
                    mma_f16(acc[mf][2 * p + 1], a[mf], bb[p][2], bb[p][3]);
                }
        }
        __syncthreads();
    }

    #pragma unroll
    for (int mf = 0; mf < 2; mf++) {
        int m = m0 + wm * 32 + mf * 16 + gi;
        #pragma unroll
        for (int nf = 0; nf < 8; nf++) {
            int n = n0 + wn * 64 + nf * 8 + 2 * tg;
            float b0v = bias[n], b1v = bias[n + 1];
            *(__half2*)(out + (size_t)m * DMODEL + n) =
                __floats2half2_rn((acc[mf][nf][0] + b0v) * scl, (acc[mf][nf][1] + b1v) * scl);
            *(__half2*)(out + (size_t)(m + 8) * DMODEL + n) =
                __floats2half2_rn((acc[mf][nf][2] + b0v) * scl, (acc[mf][nf][3] + b1v) * scl);
        }
    }
}

// ============================================================================
// attention, softmax over BATCH axis, fp16 HMMA m16n8k16.
// Block = (head, 64 q-rows), 512 threads = 16 warps (wq4 x wk4).
// K/V tiles double-buffered (cp.async overlaps compute).
// V fragments via ldmatrix.trans from [s][d] layout (no pre-transpose).
// ============================================================================
#define TP 72                       // halves per row (144B, conflict-free)
#define BTILE 9216u                 // 64*72*2 bytes, one batch tile
#define STG   36864u                // 4 batches
#define KOFF  36864u
#define VOFF  110592u
#define ATTN_SMEM 184320            // Q + 2*(K+V)
#define NIT 32

__global__ __launch_bounds__(512, 1) void attn_kernel(const float* __restrict__ mask,
                                                      float* __restrict__ out) {
    extern __shared__ char smem[];
    const uint32_t sb = s2u(smem);
    const int tid = threadIdx.x, warp = tid >> 5, lane = tid & 31;
    const int wq = warp >> 2, wk = warp & 3;
    const int gi = lane >> 2, tg = lane & 3;
    const int mi = lane >> 3, r8 = lane & 7;
    const int qb = wq * 16, kb = wk * 16;
    const int h = blockIdx.x, q0 = blockIdx.y * 64;

    const uint32_t aoff2 = (((mi & 1) * 8 + r8) * TP + (mi >> 1) * 8) * 2;   // A-pattern
    const uint32_t koff2 = (((mi >> 1) * 8 + r8) * TP + (mi & 1) * 8) * 2;   // B-pattern
    const uint32_t voff2 = (((mi & 1) * 8 + r8) * TP + (mi >> 1) * 8 + kb) * 2; // V trans

    // Q tile (resident whole kernel)
    #pragma unroll
    for (int i = 0; i < 4; i++) {
        int idx = tid + i * 512;
        int b = idx >> 9, r = (idx >> 3) & 63, ch = idx & 7;
        cpa16(sb + b * BTILE + r * 144u + ch * 16u,
              g_q + ((size_t)(b * SEQ + q0 + r) << 10) + (h << 6) + (ch << 3));
    }
    cpa_commit();

    auto issue_kv = [&](int k0, int s) {
        #pragma unroll
        for (int i = 0; i < 4; i++) {
            int idx = tid + i * 512;
            int b = idx >> 9, r = (idx >> 3) & 63, ch = idx & 7;
            cpa16(sb + KOFF + s * STG + b * BTILE + r * 144u + ch * 16u,
                  g_k + ((size_t)(b * SEQ + k0 + r) << 10) + (h << 6) + (ch << 3));
        }
        #pragma unroll
        for (int i = 0; i < 4; i++) {
            int idx = tid + i * 512;
            int b = idx >> 9, r = (idx >> 3) & 63, ch = idx & 7;
            cpa16(sb + VOFF + s * STG + b * BTILE + r * 144u + ch * 16u,
                  g_v + ((size_t)(b * SEQ + k0 + r) << 10) + (h << 6) + (ch << 3));
        }
        cpa_commit();
    };
    issue_kv(0, 0);

    float O[4][2][4];
    #pragma unroll
    for (int b = 0; b < 4; b++)
        #pragma unroll
        for (int nf = 0; nf < 2; nf++)
            #pragma unroll
            for (int c = 0; c < 4; c++) O[b][nf][c] = 0.f;

    for (int t = 0; t < NIT; t++) {
        const int s = t & 1;
        const int k0 = t * 64;
        if (t + 1 < NIT) { issue_kv((t + 1) * 64, 1 - s); cpa_wait<1>(); }
        else             { cpa_wait<0>(); }
        __syncthreads();

        // ---- S = Q K^T ----
        float S[4][2][4];
        #pragma unroll
        for (int b = 0; b < 4; b++)
            #pragma unroll
            for (int nf = 0; nf < 2; nf++)
                #pragma unroll
                for (int c = 0; c < 4; c++) S[b][nf][c] = 0.f;

        #pragma unroll
        for (int b = 0; b < 4; b++) {
            const uint32_t qbase = sb + b * BTILE + qb * 144u + aoff2;
            const uint32_t kbase = sb + KOFF + s * STG + b * BTILE + kb * 144u + koff2;
            #pragma unroll
            for (int ds = 0; ds < 4; ds++) {
                uint32_t a[4], b0, b1, b2, b3;
                ldsm4(a[0], a[1], a[2], a[3], qbase + ds * 32);
                ldsm4(b0, b1, b2, b3, kbase + ds * 32);
                mma_f16(S[b][0], a, b0, b1);
                mma_f16(S[b][1], a, b2, b3);
            }
        }
        __syncthreads();   // all K reads done; K buffer becomes P

        // ---- softmax across batch, P (fp16) into K region ----
        #pragma unroll
        for (int nf = 0; nf < 2; nf++) {
            #pragma unroll
            for (int half = 0; half < 2; half++) {
                const int ql = qb + gi + half * 8;
                const int klo = kb + nf * 8 + 2 * tg;
                const float* mptr = mask + (size_t)(q0 + ql) * SEQ + k0 + klo;
                float2 mv[4];
                #pragma unroll
                for (int b = 0; b < 4; b++)
                    mv[b] = *(const float2*)(mptr + (size_t)b * SEQ * SEQ);
                float p0[4], p1[4];
                #pragma unroll
                for (int j = 0; j < 2; j++) {
                    float z[4];
                    #pragma unroll
                    for (int b = 0; b < 4; b++) {
                        float mm = j ? mv[b].y : mv[b].x;
                        z[b] = __fadd_rn(S[b][nf][half * 2 + j], __fmul_rn(mm, -1e9f));
                    }
                    float mx = fmaxf(fmaxf(z[0], z[1]), fmaxf(z[2], z[3]));
                    float e0 = __expf(z[0] - mx), e1 = __expf(z[1] - mx);
                    float e2 = __expf(z[2] - mx), e3 = __expf(z[3] - mx);
                    float inv = __fdividef(1.0f, (e0 + e1) + (e2 + e3));
                    if (j == 0) { p0[0] = e0 * inv; p0[1] = e1 * inv; p0[2] = e2 * inv; p0[3] = e3 * inv; }
                    else        { p1[0] = e0 * inv; p1[1] = e1 * inv; p1[2] = e2 * inv; p1[3] = e3 * inv; }
                }
                #pragma unroll
                for (int b = 0; b < 4; b++)
                    *(__half2*)(smem + KOFF + s * STG + b * BTILE + ql * 144u + klo * 2) =
                        __floats2half2_rn(p0[b], p1[b]);
            }
        }
        __syncthreads();   // P visible

        // ---- O += P V  (V fragments via ldmatrix.trans on [s][d]) ----
        #pragma unroll
        for (int b = 0; b < 4; b++) {
            const uint32_t pbase = sb + KOFF + s * STG + b * BTILE + qb * 144u + aoff2;
            const uint32_t vbase = sb + VOFF + s * STG + b * BTILE + voff2;
            #pragma unroll
            for (int ks = 0; ks < 4; ks++) {
                uint32_t a[4], v0, v1, v2, v3;
                ldsm4(a[0], a[1], a[2], a[3], pbase + ks * 32);
                ldsm4t(v0, v1, v2, v3, vbase + ks * 2304u);
                mma_f16(O[b][0], a, v0, v1);
                mma_f16(O[b][1], a, v2, v3);
            }
        }
        __syncthreads();   // protect K/V stage overwrite next iter
    }

    // ---- epilogue: [B,H,S,D] -> [B,S,H*D], fp32 out ----
    #pragma unroll
    for (int b = 0; b < 4; b++) {
        #pragma unroll
        for (int nf = 0; nf < 2; nf++) {
            int dg = (h << 6) + kb + nf * 8 + 2 * tg;
            int qg = q0 + qb + gi;
            *(float2*)(out + ((size_t)b * SEQ + qg) * DMODEL + dg) =
                make_float2(O[b][nf][0], O[b][nf][1]);
            *(float2*)(out + ((size_t)b * SEQ + qg + 8) * DMODEL + dg) =
                make_float2(O[b][nf][2], O[b][nf][3]);
        }
    }
}

// ============================================================================
extern "C" void kernel_launch(void* const* d_in, const int* in_sizes, int n_in,
                              void* d_out, int out_size) {
    (void)in_sizes; (void)n_in; (void)out_size;
    const float* xq   = (const float*)d_in[0];
    const float* xk   = (const float*)d_in[1];
    const float* xv   = (const float*)d_in[2];
    const float* mask = (const float*)d_in[3];
    const float* Wq   = (const float*)d_in[4];
    const float* bq   = (const float*)d_in[5];
    const float* Wk   = (const float*)d_in[6];
    const float* bk   = (const float*)d_in[7];
    const float* Wv   = (const float*)d_in[8];
    const float* bv   = (const float*)d_in[9];
    float* out = (float*)d_out;

    cudaFuncSetAttribute(attn_kernel, cudaFuncAttributeMaxDynamicSharedMemorySize, ATTN_SMEM);

    round_x_kernel<<<dim3(8192, 3), 256>>>((const float4*)xq, (const float4*)xk, (const float4*)xv);
    wtrans_kernel<<<dim3(16, 16, 3), 256>>>(Wq, Wk, Wv);
    proj_kernel<<<dim3(DMODEL / 128, (NB * SEQ) / 128, 3), 256>>>(bq, bk, bv);
    attn_kernel<<<dim3(NH, SEQ / 64), 512, ATTN_SMEM>>>(mask, out);
}